// round 3
// baseline (speedup 1.0000x reference)
#include <cuda_runtime.h>
#include <math.h>

#define BB 32
#define NN 1024
#define CC 64
#define TOK (NN*CC)            // 65536 per batch
#define TOT (BB*NN*CC)         // 2097152
#define ROWS (BB*NN)           // 32768

// ---------------- scratch (static device memory; no runtime allocation) -------------
__device__ float g_Bm[TOT];
__device__ float g_Ei3[TOT];
__device__ float g_G[BB*CC*CC];
__device__ float g_H[4*TOT];
__device__ float g_adj[(size_t)BB*NN*NN];   // 128 MB

// =====================================================================================
// K=64 GEMM: C[b][row][j] = sum_k A[b][row][k] * W[k][j] (+bias). W optionally per-batch.
// grid (16, 32), block 256. Tile 64x64.
// =====================================================================================
__global__ __launch_bounds__(256) void k64_gemm(
    const float* __restrict__ A, const float* __restrict__ W,
    const float* __restrict__ bias, float* __restrict__ Cout, int wStride)
{
    __shared__ float As[64][65];
    __shared__ float Ws[64][65];
    const int b = blockIdx.y;
    const int row0 = blockIdx.x * 64;
    const float* Ab = A + ((size_t)b * NN + row0) * CC;
    const float* Wb = W + (size_t)b * wStride;
    const int tid = threadIdx.x;
#pragma unroll
    for (int e = 0; e < 16; e++) {
        int idx = tid + e * 256;
        int i = idx >> 6, k = idx & 63;
        As[i][k] = Ab[i * 64 + k];
        Ws[i][k] = Wb[i * 64 + k];   // Ws[k][j] layout: row index is k
    }
    __syncthreads();
    const int tx = tid & 15, ty = tid >> 4;
    float acc[4][4] = {};
#pragma unroll 16
    for (int k = 0; k < 64; k++) {
        float a[4], w[4];
#pragma unroll
        for (int r = 0; r < 4; r++) a[r] = As[ty * 4 + r][k];
#pragma unroll
        for (int c = 0; c < 4; c++) w[c] = Ws[k][tx * 4 + c];
#pragma unroll
        for (int r = 0; r < 4; r++)
#pragma unroll
            for (int c = 0; c < 4; c++) acc[r][c] = fmaf(a[r], w[c], acc[r][c]);
    }
    float bv[4] = {0.f, 0.f, 0.f, 0.f};
    if (bias) {
#pragma unroll
        for (int c = 0; c < 4; c++) bv[c] = bias[tx * 4 + c];
    }
    float* Cb = Cout + ((size_t)b * NN + row0) * CC;
#pragma unroll
    for (int r = 0; r < 4; r++)
#pragma unroll
        for (int c = 0; c < 4; c++)
            Cb[(ty * 4 + r) * 64 + tx * 4 + c] = acc[r][c] + bv[c];
}

// =====================================================================================
// Gram: G[b] += (chunk of Bm)^T (chunk of Bm) * 0.125   (K split over 8 blocks, atomics)
// grid (32, 8), block 256.
// =====================================================================================
__global__ __launch_bounds__(256) void gram_kernel(const float* __restrict__ Bm,
                                                   float* __restrict__ G)
{
    __shared__ float Bs[128][65];
    const int b = blockIdx.x, s = blockIdx.y;
    const float* Ab = Bm + ((size_t)b * NN + s * 128) * CC;
    const int tid = threadIdx.x;
#pragma unroll
    for (int e = 0; e < 32; e++) {
        int idx = tid + e * 256;
        int i = idx >> 6, k = idx & 63;
        Bs[i][k] = Ab[i * 64 + k];
    }
    __syncthreads();
    const int tx = tid & 15, ty = tid >> 4;
    float acc[4][4] = {};
#pragma unroll 8
    for (int kk = 0; kk < 128; kk++) {
        float a[4], w[4];
#pragma unroll
        for (int r = 0; r < 4; r++) a[r] = Bs[kk][ty * 4 + r];
#pragma unroll
        for (int c = 0; c < 4; c++) w[c] = Bs[kk][tx * 4 + c];
#pragma unroll
        for (int r = 0; r < 4; r++)
#pragma unroll
            for (int c = 0; c < 4; c++) acc[r][c] = fmaf(a[r], w[c], acc[r][c]);
    }
    float* Gb = G + (size_t)b * 64 * 64;
#pragma unroll
    for (int r = 0; r < 4; r++)
#pragma unroll
        for (int c = 0; c < 4; c++)
            atomicAdd(&Gb[(ty * 4 + r) * 64 + tx * 4 + c], acc[r][c] * 0.125f);
}

// =====================================================================================
// S = scale * Ei3 @ Ei3^T.  grid (8, 16, 32): 128-row x 64-col tiles, K=64, 8x4 micro.
// Dynamic smem: 128x65 + 64x65 floats = 49920 B.
// =====================================================================================
#define AAT_SMEM ((128*65 + 64*65) * 4)
__global__ __launch_bounds__(256) void aat_kernel(const float* __restrict__ E,
                                                  float* __restrict__ S, float scale)
{
    extern __shared__ float sm[];
    float (*As)[65] = (float(*)[65])sm;
    float (*Bs)[65] = (float(*)[65])(sm + 128 * 65);
    const int b = blockIdx.z;
    const int i0 = blockIdx.x * 128, j0 = blockIdx.y * 64;
    const float* Eb = E + (size_t)b * TOK;
    const int tid = threadIdx.x;
#pragma unroll
    for (int e = 0; e < 32; e++) {
        int idx = tid + e * 256;
        int i = idx >> 6, k = idx & 63;
        As[i][k] = Eb[(size_t)(i0 + i) * 64 + k];
    }
#pragma unroll
    for (int e = 0; e < 16; e++) {
        int idx = tid + e * 256;
        int j = idx >> 6, k = idx & 63;
        Bs[j][k] = Eb[(size_t)(j0 + j) * 64 + k];
    }
    __syncthreads();
    const int tx = tid & 15, ty = tid >> 4;
    float acc[8][4] = {};
#pragma unroll 8
    for (int k = 0; k < 64; k++) {
        float a[8], w[4];
#pragma unroll
        for (int r = 0; r < 8; r++) a[r] = As[ty * 8 + r][k];
#pragma unroll
        for (int c = 0; c < 4; c++) w[c] = Bs[tx * 4 + c][k];
#pragma unroll
        for (int r = 0; r < 8; r++)
#pragma unroll
            for (int c = 0; c < 4; c++) acc[r][c] = fmaf(a[r], w[c], acc[r][c]);
    }
    float* Sb = S + (size_t)b * NN * NN;
#pragma unroll
    for (int r = 0; r < 8; r++) {
        float4 v;
        v.x = acc[r][0] * scale; v.y = acc[r][1] * scale;
        v.z = acc[r][2] * scale; v.w = acc[r][3] * scale;
        *(float4*)&Sb[(size_t)(i0 + ty * 8 + r) * NN + j0 + tx * 4] = v;
    }
}

// =====================================================================================
// In-place relu + softmax over rows of 1024. grid 32768, block 256 (4 elems/thread).
// =====================================================================================
__global__ __launch_bounds__(256) void softmax_relu_kernel(float* __restrict__ S)
{
    __shared__ float sbuf[8];
    const size_t row = blockIdx.x;
    float4* p = reinterpret_cast<float4*>(S + row * NN);
    const int tid = threadIdx.x;
    float4 v = p[tid];
    v.x = fmaxf(v.x, 0.f); v.y = fmaxf(v.y, 0.f);
    v.z = fmaxf(v.z, 0.f); v.w = fmaxf(v.w, 0.f);
    float m = fmaxf(fmaxf(v.x, v.y), fmaxf(v.z, v.w));
#pragma unroll
    for (int o = 16; o > 0; o >>= 1) m = fmaxf(m, __shfl_xor_sync(0xffffffffu, m, o));
    const int lane = tid & 31, wid = tid >> 5;
    if (lane == 0) sbuf[wid] = m;
    __syncthreads();
    float M = fmaxf(fmaxf(fmaxf(sbuf[0], sbuf[1]), fmaxf(sbuf[2], sbuf[3])),
                    fmaxf(fmaxf(sbuf[4], sbuf[5]), fmaxf(sbuf[6], sbuf[7])));
    float e0 = expf(v.x - M), e1 = expf(v.y - M), e2 = expf(v.z - M), e3 = expf(v.w - M);
    float s = (e0 + e1) + (e2 + e3);
#pragma unroll
    for (int o = 16; o > 0; o >>= 1) s += __shfl_xor_sync(0xffffffffu, s, o);
    __syncthreads();
    if (lane == 0) sbuf[wid] = s;
    __syncthreads();
    float tot = ((sbuf[0] + sbuf[1]) + (sbuf[2] + sbuf[3])) +
                ((sbuf[4] + sbuf[5]) + (sbuf[6] + sbuf[7]));
    float inv = 1.0f / tot;
    v.x = e0 * inv; v.y = e1 * inv; v.z = e2 * inv; v.w = e3 * inv;
    p[tid] = v;
}

// =====================================================================================
// Diffusion GEMM: Hout[b] = Adj[b](1024x1024) @ Hin[b](1024x64).
// grid (8, 32), block 256. Tile 128x64, kc=32, 8x4 micro.
// =====================================================================================
__global__ __launch_bounds__(256) void diff_gemm(const float* __restrict__ Adj,
                                                 const float* __restrict__ Hin,
                                                 float* __restrict__ Hout)
{
    __shared__ float As[128][33];
    __shared__ float Bs[32][64];
    const int b = blockIdx.y;
    const int i0 = blockIdx.x * 128;
    const float* Ab = Adj + (size_t)b * NN * NN + (size_t)i0 * NN;
    const float* Bb = Hin + (size_t)b * TOK;
    const int tid = threadIdx.x, tx = tid & 15, ty = tid >> 4;
    float acc[8][4] = {};
    for (int c0 = 0; c0 < NN; c0 += 32) {
#pragma unroll
        for (int e = 0; e < 16; e++) {
            int idx = tid + e * 256;
            int i = idx >> 5, k = idx & 31;
            As[i][k] = Ab[(size_t)i * NN + c0 + k];
        }
#pragma unroll
        for (int e = 0; e < 8; e++) {
            int idx = tid + e * 256;
            int k = idx >> 6, j = idx & 63;
            Bs[k][j] = Bb[(size_t)(c0 + k) * 64 + j];
        }
        __syncthreads();
#pragma unroll
        for (int k = 0; k < 32; k++) {
            float4 wv = *(const float4*)&Bs[k][tx * 4];
            float w[4] = {wv.x, wv.y, wv.z, wv.w};
            float a[8];
#pragma unroll
            for (int r = 0; r < 8; r++) a[r] = As[ty * 8 + r][k];
#pragma unroll
            for (int r = 0; r < 8; r++)
#pragma unroll
                for (int c = 0; c < 4; c++) acc[r][c] = fmaf(a[r], w[c], acc[r][c]);
        }
        __syncthreads();
    }
    float* Ob = Hout + (size_t)b * TOK;
#pragma unroll
    for (int r = 0; r < 8; r++) {
        float4 v;
        v.x = acc[r][0]; v.y = acc[r][1]; v.z = acc[r][2]; v.w = acc[r][3];
        *(float4*)&Ob[(size_t)(i0 + ty * 8 + r) * 64 + tx * 4] = v;
    }
}

// =====================================================================================
// Cheb combine: out = relu( sum_k H[k] @ Wc[k] + bias + H[0] ) * bnScale
// grid 512 (64-row tiles over flattened 32768 rows), block 256.
// Dynamic smem: 4*64*65 + 64*65 floats = 83200 B.
// =====================================================================================
#define CHEB_SMEM ((4*64*65 + 64*65) * 4)
__global__ __launch_bounds__(256) void cheb_kernel(const float* __restrict__ H,
                                                   const float* __restrict__ Wc,
                                                   const float* __restrict__ bias,
                                                   float* __restrict__ Out, float bnScale)
{
    extern __shared__ float sm[];
    float* ws = sm;                                   // [4][64][65]
    float (*Hs)[65] = (float(*)[65])(sm + 4 * 64 * 65);
    const int row0 = blockIdx.x * 64;
    const int tid = threadIdx.x;
#pragma unroll
    for (int e = 0; e < 64; e++) {
        int idx = tid + e * 256;                      // 16384 weights
        int k = idx >> 12;
        int rem = idx & 4095;
        int t = rem >> 6, j = rem & 63;
        ws[(k * 64 + t) * 65 + j] = Wc[idx];
    }
    const int tx = tid & 15, ty = tid >> 4;
    float acc[4][4] = {};
    float res[4][4];
    float bv[4];
#pragma unroll
    for (int c = 0; c < 4; c++) bv[c] = bias[tx * 4 + c];
    for (int k = 0; k < 4; k++) {
        __syncthreads();
        const float* hk = H + (size_t)k * TOT + (size_t)row0 * 64;
#pragma unroll
        for (int e = 0; e < 16; e++) {
            int idx = tid + e * 256;
            int i = idx >> 6, t = idx & 63;
            Hs[i][t] = hk[i * 64 + t];
        }
        __syncthreads();
        if (k == 0) {
#pragma unroll
            for (int r = 0; r < 4; r++)
#pragma unroll
                for (int c = 0; c < 4; c++) res[r][c] = Hs[ty * 4 + r][tx * 4 + c];
        }
#pragma unroll 8
        for (int t = 0; t < 64; t++) {
            float a[4], w[4];
#pragma unroll
            for (int r = 0; r < 4; r++) a[r] = Hs[ty * 4 + r][t];
#pragma unroll
            for (int c = 0; c < 4; c++) w[c] = ws[(k * 64 + t) * 65 + tx * 4 + c];
#pragma unroll
            for (int r = 0; r < 4; r++)
#pragma unroll
                for (int c = 0; c < 4; c++) acc[r][c] = fmaf(a[r], w[c], acc[r][c]);
        }
    }
    float* ob = Out + (size_t)row0 * 64;
#pragma unroll
    for (int r = 0; r < 4; r++)
#pragma unroll
        for (int c = 0; c < 4; c++) {
            float v = acc[r][c] + res[r][c] + bv[c];
            ob[(ty * 4 + r) * 64 + tx * 4 + c] = fmaxf(v, 0.f) * bnScale;
        }
}

// =====================================================================================
// Host-side orchestration
// =====================================================================================
static void run_branch(const float* adjSrc, const float* Win, const float* bin,
                       const float* convSrc, const float* alignW, const float* alignB,
                       const float* chebW, const float* chebB, float* out,
                       float* Bm, float* G, float* Ei3, float* H, float* Adj,
                       float bnScale)
{
    dim3 g16(16, BB);
    // Bm = adjSrc @ W_in + b_in
    k64_gemm<<<g16, 256>>>(adjSrc, Win, bin, Bm, 0);
    // G = Bm^T Bm / 8  (per batch, 64x64)
    cudaMemsetAsync(G, 0, (size_t)BB * 64 * 64 * sizeof(float));
    gram_kernel<<<dim3(BB, 8), 256>>>(Bm, G);
    // Ei3 = Bm @ G   (== (Bm Bm^T / 8) @ Bm, factorized)
    k64_gemm<<<g16, 256>>>(Bm, G, nullptr, Ei3, 64 * 64);
    // S = bnScale * Ei3 Ei3^T
    aat_kernel<<<dim3(8, 16, BB), 256, AAT_SMEM>>>(Ei3, Adj, bnScale);
    // adp = softmax(relu(S)) in place
    softmax_relu_kernel<<<ROWS, 256>>>(Adj);
    // h0 = convSrc @ alignW + alignB
    k64_gemm<<<g16, 256>>>(convSrc, alignW, alignB, H, 0);
    // h1..h3 diffusion
    diff_gemm<<<dim3(8, BB), 256>>>(Adj, H, H + TOT);
    diff_gemm<<<dim3(8, BB), 256>>>(Adj, H + TOT, H + 2 * TOT);
    diff_gemm<<<dim3(8, BB), 256>>>(Adj, H + 2 * TOT, H + 3 * TOT);
    // out = relu(sum_k h_k @ Wc_k + b + h0) * bnScale
    cheb_kernel<<<ROWS / 64, 256, CHEB_SMEM>>>(H, chebW, chebB, out, bnScale);
}

extern "C" void kernel_launch(void* const* d_in, const int* in_sizes, int n_in,
                              void* d_out, int out_size)
{
    (void)in_sizes; (void)n_in; (void)out_size;
    const float* x           = (const float*)d_in[0];
    const float* sem         = (const float*)d_in[1];
    const float* t_W_in      = (const float*)d_in[4];
    const float* t_b_in      = (const float*)d_in[5];
    const float* s_W_in      = (const float*)d_in[8];
    const float* s_b_in      = (const float*)d_in[9];
    const float* x_align_W   = (const float*)d_in[10];
    const float* x_align_b   = (const float*)d_in[11];
    const float* x_cheb_W    = (const float*)d_in[12];
    const float* x_cheb_b    = (const float*)d_in[13];
    const float* sem_align_W = (const float*)d_in[14];
    const float* sem_align_b = (const float*)d_in[15];
    const float* sem_cheb_W  = (const float*)d_in[16];
    const float* sem_cheb_b  = (const float*)d_in[17];

    float *Bm, *G, *Ei3, *H, *Adj;
    cudaGetSymbolAddress((void**)&Bm, g_Bm);
    cudaGetSymbolAddress((void**)&G, g_G);
    cudaGetSymbolAddress((void**)&Ei3, g_Ei3);
    cudaGetSymbolAddress((void**)&H, g_H);
    cudaGetSymbolAddress((void**)&Adj, g_adj);

    cudaFuncSetAttribute((const void*)aat_kernel,
                         cudaFuncAttributeMaxDynamicSharedMemorySize, AAT_SMEM);
    cudaFuncSetAttribute((const void*)cheb_kernel,
                         cudaFuncAttributeMaxDynamicSharedMemorySize, CHEB_SMEM);

    const float bnScale = 1.0f / sqrtf(1.0f + 1e-5f);

    float* x_out   = (float*)d_out;          // [1,32,1024,64]
    float* sem_out = x_out + TOT;            // [1,32,1024,64]

    // sem branch: adjacency built from x with t_* weights, conv on sem
    run_branch(x, t_W_in, t_b_in, sem, sem_align_W, sem_align_b,
               sem_cheb_W, sem_cheb_b, sem_out, Bm, G, Ei3, H, Adj, bnScale);
    // x branch: adjacency built from sem with s_* weights, conv on x
    run_branch(sem, s_W_in, s_b_in, x, x_align_W, x_align_b,
               x_cheb_W, x_cheb_b, x_out, Bm, G, Ei3, H, Adj, bnScale);

    // log_p = zeros(2)
    cudaMemsetAsync(x_out + 2 * TOT, 0, 2 * sizeof(float));
}